// round 3
// baseline (speedup 1.0000x reference)
#include <cuda_runtime.h>
#include <math.h>

#define BATCH   2
#define SEQ     2048
#define DMODEL  4096
#define NHEADS  32
#define NKV     8
#define HD      128
#define GROUPQ  4
#define ROWS    (BATCH*SEQ)      // 4096
#define KVDIM   (NKV*HD)         // 1024

// Scratch (allocation-free rule: __device__ globals)
__device__ float g_Q[(size_t)ROWS * DMODEL];   // 64 MB
__device__ float g_K[(size_t)ROWS * KVDIM];    // 16 MB
__device__ float g_V[(size_t)ROWS * KVDIM];    // 16 MB
__device__ float g_A[(size_t)ROWS * DMODEL];   // 64 MB (attention output, [b,s,h*128+d])

// ---------------------------------------------------------------------------
// fp32 SGEMM: C[M,N] = A[M,K] @ B[K,N], all row-major, M%128==N%128==K%8==0
// 256 threads, 128x128 tile, BK=8, 8x8 per thread.
// ---------------------------------------------------------------------------
__global__ __launch_bounds__(256) void sgemm128(const float* __restrict__ A,
                                                const float* __restrict__ B,
                                                float* __restrict__ C,
                                                int M, int N, int K)
{
    __shared__ float As[8][128];
    __shared__ float Bs[8][128];

    int tid  = threadIdx.x;
    int tx   = tid & 15;        // 0..15
    int ty   = tid >> 4;        // 0..15
    int arow = tid >> 1;        // 0..127
    int acol = (tid & 1) * 4;   // 0 or 4
    int bR   = tid >> 5;        // 0..7
    int bC   = (tid & 31) * 4;  // 0..124

    const float* Ap = A + (size_t)(blockIdx.y * 128 + arow) * K + acol;
    const float* Bp = B + (size_t)bR * N + blockIdx.x * 128 + bC;

    float acc[8][8];
#pragma unroll
    for (int i = 0; i < 8; i++)
#pragma unroll
        for (int j = 0; j < 8; j++) acc[i][j] = 0.f;

    for (int k0 = 0; k0 < K; k0 += 8) {
        float4 a4 = *(const float4*)(Ap + k0);
        As[acol + 0][arow] = a4.x;
        As[acol + 1][arow] = a4.y;
        As[acol + 2][arow] = a4.z;
        As[acol + 3][arow] = a4.w;
        *(float4*)&Bs[bR][bC] = *(const float4*)(Bp + (size_t)k0 * N);
        __syncthreads();

#pragma unroll
        for (int kk = 0; kk < 8; kk++) {
            float ar[8], br[8];
#pragma unroll
            for (int i = 0; i < 8; i++) ar[i] = As[kk][ty * 8 + i];
#pragma unroll
            for (int j = 0; j < 8; j++) br[j] = Bs[kk][tx * 8 + j];
#pragma unroll
            for (int i = 0; i < 8; i++)
#pragma unroll
                for (int j = 0; j < 8; j++)
                    acc[i][j] = fmaf(ar[i], br[j], acc[i][j]);
        }
        __syncthreads();
    }

    float* Cp = C + (size_t)(blockIdx.y * 128 + ty * 8) * N + blockIdx.x * 128 + tx * 8;
#pragma unroll
    for (int i = 0; i < 8; i++) {
        *(float4*)(Cp + (size_t)i * N)     = make_float4(acc[i][0], acc[i][1], acc[i][2], acc[i][3]);
        *(float4*)(Cp + (size_t)i * N + 4) = make_float4(acc[i][4], acc[i][5], acc[i][6], acc[i][7]);
    }
}

// ---------------------------------------------------------------------------
// RoPE in-place: X is [ROWS, nh*128]; pair (d, d+64) rotated by angle s*invfreq
// invfreq = 10000^(-d/64), s = row % SEQ.
// ---------------------------------------------------------------------------
__global__ void rope_kernel(float* __restrict__ X, int nh, int total)
{
    int idx = blockIdx.x * blockDim.x + threadIdx.x;
    if (idx >= total) return;
    int d   = idx & 63;
    int h   = (idx >> 6) % nh;
    int row = idx / (64 * nh);
    int s   = row & (SEQ - 1);

    // inv_freq = exp(-d/64 * ln(10000))
    float inv = expf(-(float)d * (9.210340371976184f / 64.f));
    float ang = (float)s * inv;
    float sn, cs;
    sincosf(ang, &sn, &cs);

    float* p = X + (size_t)row * (nh * HD) + h * HD + d;
    float x0 = p[0], x1 = p[64];
    p[0]  = x0 * cs - x1 * sn;
    p[64] = x1 * cs + x0 * sn;
}

// ---------------------------------------------------------------------------
// Causal flash attention, fp32, online softmax.
// Grid: (SEQ/64 q-tiles, NHEADS, BATCH). Block: 256 threads.
// Q: [ROWS, DMODEL] (head h at cols h*128), K/V: [ROWS, KVDIM] (kv head kh at kh*128)
// Output written to [b, s, h*128 + d] layout (ready for @ Wo).
// ---------------------------------------------------------------------------
__global__ __launch_bounds__(256) void attn_kernel(const float* __restrict__ Q,
                                                   const float* __restrict__ K,
                                                   const float* __restrict__ V,
                                                   float* __restrict__ O)
{
    extern __shared__ float sm[];
    float* Qs   = sm;                 // 64 x 129
    float* Ks   = Qs + 64 * 129;      // 64 x 129
    float* Vs   = Ks + 64 * 129;      // 64 x 128
    float* Ss   = Vs + 64 * 128;      // 64 x 65
    float* mrow = Ss + 64 * 65;       // 64
    float* lrow = mrow + 64;          // 64
    float* arow = lrow + 64;          // 64

    int tid = threadIdx.x;
    int qb  = blockIdx.x;
    int h   = blockIdx.y;
    int b   = blockIdx.z;
    int kh  = h >> 2;                 // GQA: 4 query heads per kv head
    int q0  = qb * 64;

    const float scale = 0.08838834764831845f;  // 1/sqrt(128)

    const float* Qb = Q + (size_t)b * SEQ * DMODEL + (size_t)h * HD;
    const float* Kb = K + (size_t)b * SEQ * KVDIM + (size_t)kh * HD;
    const float* Vb = V + (size_t)b * SEQ * KVDIM + (size_t)kh * HD;

    // Load Q tile (scale folded in)
    for (int i = tid; i < 64 * 128; i += 256) {
        int r = i >> 7, c = i & 127;
        Qs[r * 129 + c] = Qb[(size_t)(q0 + r) * DMODEL + c] * scale;
    }
    if (tid < 64) { mrow[tid] = -INFINITY; lrow[tid] = 0.f; }

    float acc[32];
#pragma unroll
    for (int i = 0; i < 32; i++) acc[i] = 0.f;

    int orow = tid >> 2;          // 0..63 : output row
    int oc0  = (tid & 3) * 32;    // output col base (32 cols per thread)
    int str  = tid >> 4;          // 0..15 : score row-group
    int stc  = tid & 15;          // 0..15 : score col-group

    for (int kt = 0; kt <= qb; kt++) {
        int k0 = kt * 64;
        __syncthreads();  // protect Ks/Vs/Ss from previous tile's consumers

        for (int i = tid; i < 64 * 128; i += 256) {
            int r = i >> 7, c = i & 127;
            Ks[r * 129 + c] = Kb[(size_t)(k0 + r) * KVDIM + c];
            Vs[r * 128 + c] = Vb[(size_t)(k0 + r) * KVDIM + c];
        }
        __syncthreads();

        // Scores: 4x4 per thread, S = Qs @ Ks^T
        float s4[4][4];
#pragma unroll
        for (int i = 0; i < 4; i++)
#pragma unroll
            for (int j = 0; j < 4; j++) s4[i][j] = 0.f;

        const float* qp = &Qs[(str * 4) * 129];
        const float* kp = &Ks[(stc * 4) * 129];
#pragma unroll 4
        for (int kk = 0; kk < 128; kk++) {
            float ar[4], br[4];
#pragma unroll
            for (int i = 0; i < 4; i++) ar[i] = qp[i * 129 + kk];
#pragma unroll
            for (int j = 0; j < 4; j++) br[j] = kp[j * 129 + kk];
#pragma unroll
            for (int i = 0; i < 4; i++)
#pragma unroll
                for (int j = 0; j < 4; j++)
                    s4[i][j] = fmaf(ar[i], br[j], s4[i][j]);
        }

#pragma unroll
        for (int i = 0; i < 4; i++)
#pragma unroll
            for (int j = 0; j < 4; j++) {
                int qr = q0 + str * 4 + i;
                int kc = k0 + stc * 4 + j;
                Ss[(str * 4 + i) * 65 + stc * 4 + j] = (kc <= qr) ? s4[i][j] : -INFINITY;
            }
        __syncthreads();

        // Online-softmax row update (64 threads, one row each)
        if (tid < 64) {
            int r = tid;
            float mold = mrow[r];
            float tmax = -INFINITY;
            for (int j = 0; j < 64; j++) tmax = fmaxf(tmax, Ss[r * 65 + j]);
            float nm  = fmaxf(mold, tmax);
            float al  = expf(mold - nm);     // expf(-inf) = 0 on first tile
            float sum = 0.f;
            for (int j = 0; j < 64; j++) {
                float p = expf(Ss[r * 65 + j] - nm);
                Ss[r * 65 + j] = p;
                sum += p;
            }
            arow[r] = al;
            lrow[r] = lrow[r] * al + sum;
            mrow[r] = nm;
        }
        __syncthreads();

        // Rescale accumulator and add P @ V
        float al = arow[orow];
#pragma unroll
        for (int i = 0; i < 32; i++) acc[i] *= al;

        const float* srow = &Ss[orow * 65];
#pragma unroll 4
        for (int j = 0; j < 64; j++) {
            float p = srow[j];
            const float4* vp = (const float4*)&Vs[j * 128 + oc0];
#pragma unroll
            for (int c4 = 0; c4 < 8; c4++) {
                float4 v = vp[c4];
                acc[c4 * 4 + 0] = fmaf(p, v.x, acc[c4 * 4 + 0]);
                acc[c4 * 4 + 1] = fmaf(p, v.y, acc[c4 * 4 + 1]);
                acc[c4 * 4 + 2] = fmaf(p, v.z, acc[c4 * 4 + 2]);
                acc[c4 * 4 + 3] = fmaf(p, v.w, acc[c4 * 4 + 3]);
            }
        }
    }

    float linv = 1.f / lrow[orow];
    float* Op = O + (size_t)(b * SEQ + q0 + orow) * DMODEL + h * HD + oc0;
#pragma unroll
    for (int c4 = 0; c4 < 8; c4++) {
        float4 v = make_float4(acc[c4 * 4 + 0] * linv, acc[c4 * 4 + 1] * linv,
                               acc[c4 * 4 + 2] * linv, acc[c4 * 4 + 3] * linv);
        *(float4*)(Op + c4 * 4) = v;
    }
}

// ---------------------------------------------------------------------------
extern "C" void kernel_launch(void* const* d_in, const int* in_sizes, int n_in,
                              void* d_out, int out_size)
{
    const float* x  = (const float*)d_in[0];
    // d_in[1] = mask (causal; semantics hardcoded in attn_kernel)
    const float* Wq = (const float*)d_in[2];
    const float* Wk = (const float*)d_in[3];
    const float* Wv = (const float*)d_in[4];
    const float* Wo = (const float*)d_in[5];
    float* out = (float*)d_out;

    float *gQ, *gK, *gV, *gA;
    cudaGetSymbolAddress((void**)&gQ, g_Q);
    cudaGetSymbolAddress((void**)&gK, g_K);
    cudaGetSymbolAddress((void**)&gV, g_V);
    cudaGetSymbolAddress((void**)&gA, g_A);

    dim3 blk(256);

    // Projections
    sgemm128<<<dim3(DMODEL / 128, ROWS / 128), blk>>>(x, Wq, gQ, ROWS, DMODEL, DMODEL);
    sgemm128<<<dim3(KVDIM  / 128, ROWS / 128), blk>>>(x, Wk, gK, ROWS, KVDIM,  DMODEL);
    sgemm128<<<dim3(KVDIM  / 128, ROWS / 128), blk>>>(x, Wv, gV, ROWS, KVDIM,  DMODEL);

    // RoPE on Q (32 heads) and K (8 heads)
    {
        int totQ = ROWS * NHEADS * 64;
        int totK = ROWS * NKV * 64;
        rope_kernel<<<(totQ + 255) / 256, 256>>>(gQ, NHEADS, totQ);
        rope_kernel<<<(totK + 255) / 256, 256>>>(gK, NKV, totK);
    }

    // Causal flash attention
    size_t smem = (size_t)(64 * 129 * 2 + 64 * 128 + 64 * 65 + 3 * 64) * sizeof(float); // 116,224 B
    cudaFuncSetAttribute(attn_kernel, cudaFuncAttributeMaxDynamicSharedMemorySize, (int)smem);
    attn_kernel<<<dim3(SEQ / 64, NHEADS, BATCH), blk, smem>>>(gQ, gK, gV, gA);

    // Output projection
    sgemm128<<<dim3(DMODEL / 128, ROWS / 128), blk>>>(gA, Wo, out, ROWS, DMODEL, DMODEL);
}

// round 7
// speedup vs baseline: 1.4407x; 1.4407x over previous
#include <cuda_runtime.h>
#include <cuda_bf16.h>
#include <math.h>
#include <stdint.h>

#define BATCH   2
#define SEQ     2048
#define DMODEL  4096
#define NHEADS  32
#define NKV     8
#define HD      128
#define ROWS    (BATCH*SEQ)      // 4096
#define KVDIM   (NKV*HD)         // 1024

// ---------------- scratch (__device__ globals: allocation-free rule) -------
__device__ float g_Q[(size_t)ROWS * DMODEL];
__device__ float g_K[(size_t)ROWS * KVDIM];
__device__ float g_V[(size_t)ROWS * KVDIM];
__device__ float g_A[(size_t)ROWS * DMODEL];

__device__ __align__(16) __nv_bfloat16 g_Xhi[(size_t)ROWS * DMODEL];
__device__ __align__(16) __nv_bfloat16 g_Xlo[(size_t)ROWS * DMODEL];
__device__ __align__(16) __nv_bfloat16 g_Wqh[(size_t)DMODEL * DMODEL]; // [N,K]
__device__ __align__(16) __nv_bfloat16 g_Wql[(size_t)DMODEL * DMODEL];
__device__ __align__(16) __nv_bfloat16 g_Wkh[(size_t)KVDIM * DMODEL];
__device__ __align__(16) __nv_bfloat16 g_Wkl[(size_t)KVDIM * DMODEL];
__device__ __align__(16) __nv_bfloat16 g_Wvh[(size_t)KVDIM * DMODEL];
__device__ __align__(16) __nv_bfloat16 g_Wvl[(size_t)KVDIM * DMODEL];
__device__ __align__(16) __nv_bfloat16 g_Woh[(size_t)DMODEL * DMODEL];
__device__ __align__(16) __nv_bfloat16 g_Wol[(size_t)DMODEL * DMODEL];

// ---------------- PTX helpers (sm_80-era ISA only: valid on compute_103) ---
__device__ __forceinline__ uint32_t smem_u32(const void* p) {
    uint32_t a;
    asm("{ .reg .u64 t; cvta.to.shared.u64 t, %1; cvt.u32.u64 %0, t; }" : "=r"(a) : "l"(p));
    return a;
}
__device__ __forceinline__ void cp16(uint32_t s, const void* g) {
    asm volatile("cp.async.cg.shared.global [%0], [%1], 16;" :: "r"(s), "l"(g));
}
#define CP_COMMIT() asm volatile("cp.async.commit_group;" ::: "memory")
#define CP_WAIT0()  asm volatile("cp.async.wait_group 0;" ::: "memory")
#define CP_WAIT1()  asm volatile("cp.async.wait_group 1;" ::: "memory")

__device__ __forceinline__ void ldm_x4(uint32_t* r, uint32_t a) {
    asm volatile("ldmatrix.sync.aligned.m8n8.x4.shared.b16 {%0,%1,%2,%3}, [%4];"
                 : "=r"(r[0]), "=r"(r[1]), "=r"(r[2]), "=r"(r[3]) : "r"(a));
}
__device__ __forceinline__ void ldm_x2(uint32_t* r, uint32_t a) {
    asm volatile("ldmatrix.sync.aligned.m8n8.x2.shared.b16 {%0,%1}, [%2];"
                 : "=r"(r[0]), "=r"(r[1]) : "r"(a));
}
__device__ __forceinline__ void mma16816(float* d, const uint32_t* a, const uint32_t* b) {
    asm volatile(
        "mma.sync.aligned.m16n8k16.row.col.f32.bf16.bf16.f32 "
        "{%0,%1,%2,%3}, {%4,%5,%6,%7}, {%8,%9}, {%0,%1,%2,%3};"
        : "+f"(d[0]), "+f"(d[1]), "+f"(d[2]), "+f"(d[3])
        : "r"(a[0]), "r"(a[1]), "r"(a[2]), "r"(a[3]), "r"(b[0]), "r"(b[1]));
}

// ---------------- precision-split conversion kernels ----------------------
__global__ void conv_split(const float* __restrict__ X, __nv_bfloat16* __restrict__ hi,
                           __nv_bfloat16* __restrict__ lo, int total4)
{
    int i = blockIdx.x * blockDim.x + threadIdx.x;
    if (i >= total4) return;
    float4 v = ((const float4*)X)[i];
    float f[4] = {v.x, v.y, v.z, v.w};
    __nv_bfloat16 h[4], l[4];
#pragma unroll
    for (int j = 0; j < 4; j++) {
        h[j] = __float2bfloat16(f[j]);
        l[j] = __float2bfloat16(f[j] - __bfloat162float(h[j]));
    }
    ((uint2*)hi)[i] = *(uint2*)h;
    ((uint2*)lo)[i] = *(uint2*)l;
}

// W[K,N] fp32 -> hi/lo bf16 [N,K] (transposed)
__global__ void conv_split_T(const float* __restrict__ W, __nv_bfloat16* __restrict__ hi,
                             __nv_bfloat16* __restrict__ lo, int K, int N)
{
    __shared__ float t[32][33];
    int n0 = blockIdx.x * 32, k0 = blockIdx.y * 32;
    int tx = threadIdx.x, ty = threadIdx.y;
#pragma unroll
    for (int i = 0; i < 32; i += 8)
        t[ty + i][tx] = W[(size_t)(k0 + ty + i) * N + n0 + tx];
    __syncthreads();
#pragma unroll
    for (int i = 0; i < 32; i += 8) {
        float v = t[tx][ty + i];                 // = W[k0+tx][n0+ty+i]
        __nv_bfloat16 h = __float2bfloat16(v);
        size_t o = (size_t)(n0 + ty + i) * K + k0 + tx;
        hi[o] = h;
        lo[o] = __float2bfloat16(v - __bfloat162float(h));
    }
}

// ---------------- mma.sync split-bf16 GEMM ---------------------------------
// C[M,N] = A[M,K] @ B[N,K]^T, A/B as (hi,lo) bf16, C fp32.
// Block 128x128, BK=32, 8 warps (2x4), warp tile 64x32, 2-stage cp.async.
#define TSTRIDE 80                       // bytes per smem row (conflict-free)
#define TILE_B  (128 * TSTRIDE)          // 10240 B per operand tile
#define STAGE_B (4 * TILE_B)             // Ah, Al, Bh, Bl
#define GEMM_SMEM (2 * STAGE_B)          // 81920 B

__device__ __forceinline__ void ld_stage(uint32_t sst,
    const __nv_bfloat16* __restrict__ Ah, const __nv_bfloat16* __restrict__ Al,
    const __nv_bfloat16* __restrict__ Bh, const __nv_bfloat16* __restrict__ Bl,
    int m0, int n0, int K, int k0, int tid)
{
#pragma unroll
    for (int it = 0; it < 2; it++) {
        int ch = tid + it * 256;         // 0..511
        int r  = ch >> 2;
        int j  = ch & 3;
        uint32_t so = (uint32_t)(r * TSTRIDE + j * 16);
        size_t Ao = (size_t)(m0 + r) * K + k0 + j * 8;
        size_t Bo = (size_t)(n0 + r) * K + k0 + j * 8;
        cp16(sst + so,              Ah + Ao);
        cp16(sst + TILE_B + so,     Al + Ao);
        cp16(sst + 2 * TILE_B + so, Bh + Bo);
        cp16(sst + 3 * TILE_B + so, Bl + Bo);
    }
}

__global__ __launch_bounds__(256) void gemm_mma(
    const __nv_bfloat16* __restrict__ Ahi, const __nv_bfloat16* __restrict__ Alo,
    const __nv_bfloat16* __restrict__ Bhi, const __nv_bfloat16* __restrict__ Blo,
    float* __restrict__ C, int M, int N, int K)
{
    extern __shared__ char smc[];
    uint32_t smb = smem_u32(smc);
    int tid  = threadIdx.x;
    int lane = tid & 31, wid = tid >> 5;
    int m0 = blockIdx.y * 128, n0 = blockIdx.x * 128;
    int wm = (wid & 1) * 64;             // warp m offset in tile
    int wn = (wid >> 1) * 32;            // warp n offset in tile

    // ldmatrix per-lane addressing
    int aR = wm + (lane & 15);           // A row for this lane
    int aC = (lane >> 4);                // A chunk half (0/1)
    int bR = wn + (lane & 7);            // B row
    int bC = (lane >> 3) & 1;            // B chunk half

    float acc[4][4][4];
#pragma unroll
    for (int mt = 0; mt < 4; mt++)
#pragma unroll
        for (int nt = 0; nt < 4; nt++)
#pragma unroll
            for (int q = 0; q < 4; q++) acc[mt][nt][q] = 0.f;

    int NC = K >> 5;                     // chunks of 32
    ld_stage(smb, Ahi, Alo, Bhi, Blo, m0, n0, K, 0, tid);
    CP_COMMIT();

    for (int c = 0; c < NC; c++) {
        if (c + 1 < NC) {
            ld_stage(smb + ((c + 1) & 1) * STAGE_B, Ahi, Alo, Bhi, Blo,
                     m0, n0, K, (c + 1) << 5, tid);
            CP_COMMIT();
            CP_WAIT1();
        } else {
            CP_WAIT0();
        }
        __syncthreads();

        uint32_t sst = smb + (c & 1) * STAGE_B;
#pragma unroll
        for (int ks = 0; ks < 2; ks++) {     // k16 halves of the 32-chunk
            int jb = ks * 2;                 // chunk base (16B units)
            uint32_t ah[4][4], bh[4][2];
#pragma unroll
            for (int mt = 0; mt < 4; mt++)
                ldm_x4(ah[mt], sst + (uint32_t)((aR + mt * 16) * TSTRIDE + (jb + aC) * 16));
#pragma unroll
            for (int nt = 0; nt < 4; nt++)
                ldm_x2(bh[nt], sst + 2 * TILE_B + (uint32_t)((bR + nt * 8) * TSTRIDE + (jb + bC) * 16));
#pragma unroll
            for (int mt = 0; mt < 4; mt++)
#pragma unroll
                for (int nt = 0; nt < 4; nt++)
                    mma16816(acc[mt][nt], ah[mt], bh[nt]);

            uint32_t bl[4][2];
#pragma unroll
            for (int nt = 0; nt < 4; nt++)
                ldm_x2(bl[nt], sst + 3 * TILE_B + (uint32_t)((bR + nt * 8) * TSTRIDE + (jb + bC) * 16));
#pragma unroll
            for (int mt = 0; mt < 4; mt++)
#pragma unroll
                for (int nt = 0; nt < 4; nt++)
                    mma16816(acc[mt][nt], ah[mt], bl[nt]);

            uint32_t al[4][4];
#pragma unroll
            for (int mt = 0; mt < 4; mt++)
                ldm_x4(al[mt], sst + TILE_B + (uint32_t)((aR + mt * 16) * TSTRIDE + (jb + aC) * 16));
#pragma unroll
            for (int mt = 0; mt < 4; mt++)
#pragma unroll
                for (int nt = 0; nt < 4; nt++)
                    mma16816(acc[mt][nt], al[mt], bh[nt]);
        }
        __syncthreads();
    }

    // Epilogue: mma acc layout -> C
    int gr = lane >> 2, gc = (lane & 3) * 2;
#pragma unroll
    for (int mt = 0; mt < 4; mt++) {
#pragma unroll
        for (int nt = 0; nt < 4; nt++) {
            size_t r0 = (size_t)(m0 + wm + mt * 16 + gr) * N + n0 + wn + nt * 8 + gc;
            size_t r1 = r0 + (size_t)8 * N;
            *(float2*)(C + r0) = make_float2(acc[mt][nt][0], acc[mt][nt][1]);
            *(float2*)(C + r1) = make_float2(acc[mt][nt][2], acc[mt][nt][3]);
        }
    }
}

// ---------------- RoPE (unchanged) -----------------------------------------
__global__ void rope_kernel(float* __restrict__ X, int nh, int total)
{
    int idx = blockIdx.x * blockDim.x + threadIdx.x;
    if (idx >= total) return;
    int d   = idx & 63;
    int h   = (idx >> 6) % nh;
    int row = idx / (64 * nh);
    int s   = row & (SEQ - 1);
    float inv = expf(-(float)d * (9.210340371976184f / 64.f));
    float sn, cs;
    sincosf((float)s * inv, &sn, &cs);
    float* p = X + (size_t)row * (nh * HD) + h * HD + d;
    float x0 = p[0], x1 = p[64];
    p[0]  = x0 * cs - x1 * sn;
    p[64] = x1 * cs + x0 * sn;
}

// ---------------- fp32 causal flash attention (unchanged, passing) ---------
__global__ __launch_bounds__(256) void attn_kernel(const float* __restrict__ Q,
                                                   const float* __restrict__ K,
                                                   const float* __restrict__ V,
                                                   float* __restrict__ O)
{
    extern __shared__ float smf[];
    float* Qs   = smf;
    float* Ks   = Qs + 64 * 129;
    float* Vs   = Ks + 64 * 129;
    float* Ss   = Vs + 64 * 128;
    float* mrow = Ss + 64 * 65;
    float* lrow = mrow + 64;
    float* arow = lrow + 64;

    int tid = threadIdx.x;
    int qb  = blockIdx.x;
    int h   = blockIdx.y;
    int b   = blockIdx.z;
    int kh  = h >> 2;
    int q0  = qb * 64;
    const float scale = 0.08838834764831845f;

    const float* Qb = Q + (size_t)b * SEQ * DMODEL + (size_t)h * HD;
    const float* Kb = K + (size_t)b * SEQ * KVDIM + (size_t)kh * HD;
    const float* Vb = V + (size_t)b * SEQ * KVDIM + (size_t)kh * HD;

    for (int i = tid; i < 64 * 128; i += 256) {
        int r = i >> 7, c = i & 127;
        Qs[r * 129 + c] = Qb[(size_t)(q0 + r) * DMODEL + c] * scale;
    }
    if (tid < 64) { mrow[tid] = -INFINITY; lrow[tid] = 0.f; }

    float acc[32];
#pragma unroll
    for (int i = 0; i < 32; i++) acc[i] = 0.f;

    int orow = tid >> 2;
    int oc0  = (tid & 3) * 32;
    int str  = tid >> 4;
    int stc  = tid & 15;

    for (int kt = 0; kt <= qb; kt++) {
        int k0 = kt * 64;
        __syncthreads();
        for (int i = tid; i < 64 * 128; i += 256) {
            int r = i >> 7, c = i & 127;
            Ks[r * 129 + c] = Kb[(size_t)(k0 + r) * KVDIM + c];
            Vs[r * 128 + c] = Vb[(size_t)(k0 + r) * KVDIM + c];
        }
        __syncthreads();

        float s4[4][4];
#pragma unroll
        for (int i = 0; i < 4; i++)
#pragma unroll
            for (int j = 0; j < 4; j++) s4[i][j] = 0.f;

        const float* qp = &Qs[(str * 4) * 129];
        const float* kp = &Ks[(stc * 4) * 129];
#pragma unroll 4
        for (int kk = 0; kk < 128; kk++) {
            float ar[4], br[4];
#pragma unroll
            for (int i = 0; i < 4; i++) ar[i] = qp[i * 129 + kk];
#pragma unroll
            for (int j = 0; j < 4; j++) br[j] = kp[j * 129 + kk];
#pragma unroll
            for (int i = 0; i < 4; i++)
#pragma unroll
                for (int j = 0; j < 4; j++)
                    s4[i][j] = fmaf(ar[i], br[j], s4[i][j]);
        }

#pragma unroll
        for (int i = 0; i < 4; i++)
#pragma unroll
            for (int j = 0; j < 4; j++) {
                int qr = q0 + str * 4 + i;
                int kc = k0 + stc * 4 + j;
                Ss[(str * 4 + i) * 65 + stc * 4 + j] = (kc <= qr) ? s4[i][j] : -INFINITY;
            }
        __syncthreads();

        if (tid < 64) {
            int r = tid;
            float mold = mrow[r];
            float tmax = -INFINITY;
            for (int j = 0; j < 64; j++) tmax = fmaxf(tmax, Ss[r * 65 + j]);
            float nm  = fmaxf(mold, tmax);
            float al  = expf(mold - nm);
            float sum = 0.f;
            for (int j = 0; j < 64; j++) {
                float p = expf(Ss[r * 65 + j] - nm);
                Ss[r * 65 + j] = p;
                sum += p;
            }
            arow[r] = al;
            lrow[r] = lrow[r] * al + sum;
            mrow[r] = nm;
        }
        __syncthreads();

        float al = arow[orow];
#pragma unroll
        for (int i = 0; i < 32; i++) acc[i] *= al;

        const float* srow = &Ss[orow * 65];
#pragma unroll 4
        for (int j = 0; j < 64; j++) {
            float p = srow[j];
            const float4* vp = (const float4*)&Vs[j * 128 + oc0];
#pragma unroll
            for (int c4 = 0; c4 < 8; c4++) {
                float4 v = vp[c4];
                acc[c4 * 4 + 0] = fmaf(p, v.x, acc[c4 * 4 + 0]);
                acc[c4 * 4 + 1] = fmaf(p, v.y, acc[c4 * 4 + 1]);
                acc[c4 * 4 + 2] = fmaf(p, v.z, acc[c4 * 4 + 2]);
                acc[c4 * 4 + 3] = fmaf(p, v.w, acc[c4 * 4 + 3]);
            }
        }
    }

    float linv = 1.f / lrow[orow];
    float* Op = O + (size_t)(b * SEQ + q0 + orow) * DMODEL + h * HD + oc0;
#pragma unroll
    for (int c4 = 0; c4 < 8; c4++) {
        *(float4*)(Op + c4 * 4) = make_float4(acc[c4 * 4 + 0] * linv, acc[c4 * 4 + 1] * linv,
                                              acc[c4 * 4 + 2] * linv, acc[c4 * 4 + 3] * linv);
    }
}

// ---------------------------------------------------------------------------
extern "C" void kernel_launch(void* const* d_in, const int* in_sizes, int n_in,
                              void* d_out, int out_size)
{
    const float* x  = (const float*)d_in[0];
    const float* Wq = (const float*)d_in[2];
    const float* Wk = (const float*)d_in[3];
    const float* Wv = (const float*)d_in[4];
    const float* Wo = (const float*)d_in[5];
    float* out = (float*)d_out;

    float *gQ, *gK, *gV, *gA;
    __nv_bfloat16 *xh, *xl, *wqh, *wql, *wkh, *wkl, *wvh, *wvl, *woh, *wol;
    cudaGetSymbolAddress((void**)&gQ, g_Q);
    cudaGetSymbolAddress((void**)&gK, g_K);
    cudaGetSymbolAddress((void**)&gV, g_V);
    cudaGetSymbolAddress((void**)&gA, g_A);
    cudaGetSymbolAddress((void**)&xh, g_Xhi);
    cudaGetSymbolAddress((void**)&xl, g_Xlo);
    cudaGetSymbolAddress((void**)&wqh, g_Wqh);
    cudaGetSymbolAddress((void**)&wql, g_Wql);
    cudaGetSymbolAddress((void**)&wkh, g_Wkh);
    cudaGetSymbolAddress((void**)&wkl, g_Wkl);
    cudaGetSymbolAddress((void**)&wvh, g_Wvh);
    cudaGetSymbolAddress((void**)&wvl, g_Wvl);
    cudaGetSymbolAddress((void**)&woh, g_Woh);
    cudaGetSymbolAddress((void**)&wol, g_Wol);

    cudaFuncSetAttribute(gemm_mma, cudaFuncAttributeMaxDynamicSharedMemorySize, GEMM_SMEM);

    // Split conversions
    int tot4 = ROWS * DMODEL / 4;
    conv_split<<<(tot4 + 255) / 256, 256>>>(x, xh, xl, tot4);
    conv_split_T<<<dim3(DMODEL / 32, DMODEL / 32), dim3(32, 8)>>>(Wq, wqh, wql, DMODEL, DMODEL);
    conv_split_T<<<dim3(KVDIM / 32, DMODEL / 32), dim3(32, 8)>>>(Wk, wkh, wkl, DMODEL, KVDIM);
    conv_split_T<<<dim3(KVDIM / 32, DMODEL / 32), dim3(32, 8)>>>(Wv, wvh, wvl, DMODEL, KVDIM);
    conv_split_T<<<dim3(DMODEL / 32, DMODEL / 32), dim3(32, 8)>>>(Wo, woh, wol, DMODEL, DMODEL);

    // Projections on HMMA (split-bf16, 3 mma products)
    gemm_mma<<<dim3(DMODEL / 128, ROWS / 128), 256, GEMM_SMEM>>>(xh, xl, wqh, wql, gQ, ROWS, DMODEL, DMODEL);
    gemm_mma<<<dim3(KVDIM / 128, ROWS / 128), 256, GEMM_SMEM>>>(xh, xl, wkh, wkl, gK, ROWS, KVDIM, DMODEL);
    gemm_mma<<<dim3(KVDIM / 128, ROWS / 128), 256, GEMM_SMEM>>>(xh, xl, wvh, wvl, gV, ROWS, KVDIM, DMODEL);

    // RoPE
    {
        int totQ = ROWS * NHEADS * 64;
        int totK = ROWS * NKV * 64;
        rope_kernel<<<(totQ + 255) / 256, 256>>>(gQ, NHEADS, totQ);
        rope_kernel<<<(totK + 255) / 256, 256>>>(gK, NKV, totK);
    }

    // Causal flash attention (fp32)
    size_t smem = (size_t)(64 * 129 * 2 + 64 * 128 + 64 * 65 + 3 * 64) * sizeof(float);
    cudaFuncSetAttribute(attn_kernel, cudaFuncAttributeMaxDynamicSharedMemorySize, (int)smem);
    attn_kernel<<<dim3(SEQ / 64, NHEADS, BATCH), 256, smem>>>(gQ, gK, gV, gA);

    // Output projection: split attn output (reuse X buffers), then HMMA GEMM
    conv_split<<<(tot4 + 255) / 256, 256>>>(gA, xh, xl, tot4);
    gemm_mma<<<dim3(DMODEL / 128, ROWS / 128), 256, GEMM_SMEM>>>(xh, xl, woh, wol, out, ROWS, DMODEL, DMODEL);
}

// round 11
// speedup vs baseline: 1.5888x; 1.1029x over previous
#include <cuda_runtime.h>
#include <cuda_fp16.h>
#include <math.h>
#include <stdint.h>

#define BATCH   2
#define SEQ     2048
#define DMODEL  4096
#define NHEADS  32
#define NKV     8
#define HD      128
#define ROWS    (BATCH*SEQ)      // 4096
#define KVDIM   (NKV*HD)         // 1024

// ---------------- scratch (__device__ globals: allocation-free rule) -------
__device__ float g_Q[(size_t)ROWS * DMODEL];
__device__ float g_K[(size_t)ROWS * KVDIM];
__device__ float g_V[(size_t)ROWS * KVDIM];
__device__ float g_A[(size_t)ROWS * DMODEL];

__device__ __align__(16) __half g_Xhi[(size_t)ROWS * DMODEL];
__device__ __align__(16) __half g_Xlo[(size_t)ROWS * DMODEL];
__device__ __align__(16) __half g_Wq[(size_t)DMODEL * DMODEL];  // [N,K] fp16
__device__ __align__(16) __half g_Wk[(size_t)KVDIM * DMODEL];
__device__ __align__(16) __half g_Wv[(size_t)KVDIM * DMODEL];
__device__ __align__(16) __half g_Wo[(size_t)DMODEL * DMODEL];

// ---------------- PTX helpers (sm_80-era ISA: valid on compute_103) --------
__device__ __forceinline__ uint32_t smem_u32(const void* p) {
    uint32_t a;
    asm("{ .reg .u64 t; cvta.to.shared.u64 t, %1; cvt.u32.u64 %0, t; }" : "=r"(a) : "l"(p));
    return a;
}
__device__ __forceinline__ void cp16(uint32_t s, const void* g) {
    asm volatile("cp.async.cg.shared.global [%0], [%1], 16;" :: "r"(s), "l"(g));
}
#define CP_COMMIT() asm volatile("cp.async.commit_group;" ::: "memory")
#define CP_WAIT0()  asm volatile("cp.async.wait_group 0;" ::: "memory")
#define CP_WAIT1()  asm volatile("cp.async.wait_group 1;" ::: "memory")

__device__ __forceinline__ void ldm_x4(uint32_t* r, uint32_t a) {
    asm volatile("ldmatrix.sync.aligned.m8n8.x4.shared.b16 {%0,%1,%2,%3}, [%4];"
                 : "=r"(r[0]), "=r"(r[1]), "=r"(r[2]), "=r"(r[3]) : "r"(a));
}
__device__ __forceinline__ void ldm_x2(uint32_t* r, uint32_t a) {
    asm volatile("ldmatrix.sync.aligned.m8n8.x2.shared.b16 {%0,%1}, [%2];"
                 : "=r"(r[0]), "=r"(r[1]) : "r"(a));
}
__device__ __forceinline__ void mma16816(float* d, const uint32_t* a, const uint32_t* b) {
    asm volatile(
        "mma.sync.aligned.m16n8k16.row.col.f32.f16.f16.f32 "
        "{%0,%1,%2,%3}, {%4,%5,%6,%7}, {%8,%9}, {%0,%1,%2,%3};"
        : "+f"(d[0]), "+f"(d[1]), "+f"(d[2]), "+f"(d[3])
        : "r"(a[0]), "r"(a[1]), "r"(a[2]), "r"(a[3]), "r"(b[0]), "r"(b[1]));
}

// ---------------- precision-split conversion kernels ----------------------
// X fp32 -> hi fp16 + lo fp16 (residual)
__global__ void conv_split_half(const float* __restrict__ X, __half* __restrict__ hi,
                                __half* __restrict__ lo, int total4)
{
    int i = blockIdx.x * blockDim.x + threadIdx.x;
    if (i >= total4) return;
    float4 v = ((const float4*)X)[i];
    float f[4] = {v.x, v.y, v.z, v.w};
    __half h[4], l[4];
#pragma unroll
    for (int j = 0; j < 4; j++) {
        h[j] = __float2half_rn(f[j]);
        l[j] = __float2half_rn(f[j] - __half2float(h[j]));
    }
    ((uint2*)hi)[i] = *(uint2*)h;
    ((uint2*)lo)[i] = *(uint2*)l;
}

// W[K,N] fp32 -> fp16 [N,K] (transposed, hi only)
__global__ void conv_T_half(const float* __restrict__ W, __half* __restrict__ hi,
                            int K, int N)
{
    __shared__ float t[32][33];
    int n0 = blockIdx.x * 32, k0 = blockIdx.y * 32;
    int tx = threadIdx.x, ty = threadIdx.y;
#pragma unroll
    for (int i = 0; i < 32; i += 8)
        t[ty + i][tx] = W[(size_t)(k0 + ty + i) * N + n0 + tx];
    __syncthreads();
#pragma unroll
    for (int i = 0; i < 32; i += 8) {
        float v = t[tx][ty + i];                 // = W[k0+tx][n0+ty+i]
        hi[(size_t)(n0 + ty + i) * K + k0 + tx] = __float2half_rn(v);
    }
}

// ---------------- mma.sync fp16 2-product GEMM -----------------------------
// C[M,N] = (Ahi+Alo)[M,K] @ Bhi[N,K]^T, fp32 accum.
// Block 128x128, BK=32, 8 warps (2x4), warp tile 64x32, 3-stage cp.async.
#define TSTRIDE 80                       // bytes per smem row (conflict-free)
#define TILE_B  (128 * TSTRIDE)          // 10240 B per operand tile (32 fp16 cols)
#define STAGE_B (3 * TILE_B)             // Ah, Al, Bh = 30720 B
#define GEMM_SMEM (3 * STAGE_B)          // 3 stages = 92160 B

__device__ __forceinline__ void ld_stage(uint32_t sst,
    const __half* __restrict__ Ah, const __half* __restrict__ Al,
    const __half* __restrict__ Bh, int m0, int n0, int K, int k0, int tid)
{
#pragma unroll
    for (int it = 0; it < 6; it++) {
        int idx  = tid + it * 256;       // 0..1535
        int tile = idx >> 9;             // 0..2
        int r    = (idx >> 2) & 127;
        int j    = idx & 3;
        const __half* g = (tile == 0) ? Ah : ((tile == 1) ? Al : Bh);
        int row0 = (tile == 2) ? n0 : m0;
        cp16(sst + (uint32_t)(tile * TILE_B + r * TSTRIDE + j * 16),
             g + (size_t)(row0 + r) * K + k0 + j * 8);
    }
}

__global__ __launch_bounds__(256, 2) void gemm_mma(
    const __half* __restrict__ Ahi, const __half* __restrict__ Alo,
    const __half* __restrict__ Bhi,
    float* __restrict__ C, int M, int N, int K)
{
    extern __shared__ char smc[];
    uint32_t smb = smem_u32(smc);
    int tid  = threadIdx.x;
    int lane = tid & 31, wid = tid >> 5;
    int m0 = blockIdx.y * 128, n0 = blockIdx.x * 128;
    int wm = (wid & 1) * 64;             // warp m offset in tile
    int wn = (wid >> 1) * 32;            // warp n offset in tile

    int aR = wm + (lane & 15);           // ldmatrix A row for this lane
    int aC = (lane >> 4);                // A 16B-chunk half
    int bR = wn + (lane & 7);            // B row
    int bC = (lane >> 3) & 1;            // B 16B-chunk half

    float acc[4][4][4];
#pragma unroll
    for (int mt = 0; mt < 4; mt++)
#pragma unroll
        for (int nt = 0; nt < 4; nt++)
#pragma unroll
            for (int q = 0; q < 4; q++) acc[mt][nt][q] = 0.f;

    int NC = K >> 5;                     // chunks of 32

    // Preload chunks 0,1 into stages 0,1
    ld_stage(smb,           Ahi, Alo, Bhi, m0, n0, K, 0,  tid); CP_COMMIT();
    ld_stage(smb + STAGE_B, Ahi, Alo, Bhi, m0, n0, K, 32, tid); CP_COMMIT();

    for (int c = 0; c < NC; c++) {
        // wait for chunk c (newest-1 normally, newest at last iter)
        if (c + 1 < NC) CP_WAIT1(); else CP_WAIT0();
        __syncthreads();                 // visibility + frees stage (c-1)%3

        // prefetch chunk c+2 into stage (c+2)%3 (buffer freed by barrier above)
        if (c + 2 < NC) {
            ld_stage(smb + (uint32_t)(((c + 2) % 3) * STAGE_B),
                     Ahi, Alo, Bhi, m0, n0, K, (c + 2) << 5, tid);
            CP_COMMIT();
        }

        uint32_t sst = smb + (uint32_t)((c % 3) * STAGE_B);
#pragma unroll
        for (int ks = 0; ks < 2; ks++) {     // k16 halves of the 32-chunk
            int jb = ks * 2;                 // 16B units
            uint32_t ah[4][4], al[4][4], bh[4][2];
#pragma unroll
            for (int mt = 0; mt < 4; mt++)
                ldm_x4(ah[mt], sst + (uint32_t)((aR + mt * 16) * TSTRIDE + (jb + aC) * 16));
#pragma unroll
            for (int nt = 0; nt < 4; nt++)
                ldm_x2(bh[nt], sst + 2 * TILE_B + (uint32_t)((bR + nt * 8) * TSTRIDE + (jb + bC) * 16));
#pragma unroll
            for (int mt = 0; mt < 4; mt++)
                ldm_x4(al[mt], sst + TILE_B + (uint32_t)((aR + mt * 16) * TSTRIDE + (jb + aC) * 16));
#pragma unroll
            for (int mt = 0; mt < 4; mt++)
#pragma unroll
                for (int nt = 0; nt < 4; nt++)
                    mma16816(acc[mt][nt], ah[mt], bh[nt]);
#pragma unroll
            for (int mt = 0; mt < 4; mt++)
#pragma unroll
                for (int nt = 0; nt < 4; nt++)
                    mma16816(acc[mt][nt], al[mt], bh[nt]);
        }
    }

    // Epilogue: mma acc layout -> C
    int gr = lane >> 2, gc = (lane & 3) * 2;
#pragma unroll
    for (int mt = 0; mt < 4; mt++) {
#pragma unroll
        for (int nt = 0; nt < 4; nt++) {
            size_t r0 = (size_t)(m0 + wm + mt * 16 + gr) * N + n0 + wn + nt * 8 + gc;
            size_t r1 = r0 + (size_t)8 * N;
            *(float2*)(C + r0) = make_float2(acc[mt][nt][0], acc[mt][nt][1]);
            *(float2*)(C + r1) = make_float2(acc[mt][nt][2], acc[mt][nt][3]);
        }
    }
}

// ---------------- RoPE (unchanged) -----------------------------------------
__global__ void rope_kernel(float* __restrict__ X, int nh, int total)
{
    int idx = blockIdx.x * blockDim.x + threadIdx.x;
    if (idx >= total) return;
    int d   = idx & 63;
    int h   = (idx >> 6) % nh;
    int row = idx / (64 * nh);
    int s   = row & (SEQ - 1);
    float inv = expf(-(float)d * (9.210340371976184f / 64.f));
    float sn, cs;
    sincosf((float)s * inv, &sn, &cs);
    float* p = X + (size_t)row * (nh * HD) + h * HD + d;
    float x0 = p[0], x1 = p[64];
    p[0]  = x0 * cs - x1 * sn;
    p[64] = x1 * cs + x0 * sn;
}

// ---------------- fp32 causal flash attention (unchanged, passing) ---------
__global__ __launch_bounds__(256) void attn_kernel(const float* __restrict__ Q,
                                                   const float* __restrict__ K,
                                                   const float* __restrict__ V,
                                                   float* __restrict__ O)
{
    extern __shared__ float smf[];
    float* Qs   = smf;
    float* Ks   = Qs + 64 * 129;
    float* Vs   = Ks + 64 * 129;
    float* Ss   = Vs + 64 * 128;
    float* mrow = Ss + 64 * 65;
    float* lrow = mrow + 64;
    float* arow = lrow + 64;

    int tid = threadIdx.x;
    int qb  = blockIdx.x;
    int h   = blockIdx.y;
    int b   = blockIdx.z;
    int kh  = h >> 2;
    int q0  = qb * 64;
    const float scale = 0.08838834764831845f;

    const float* Qb = Q + (size_t)b * SEQ * DMODEL + (size_t)h * HD;
    const float* Kb = K + (size_t)b * SEQ * KVDIM + (size_t)kh * HD;
    const float* Vb = V + (size_t)b * SEQ * KVDIM + (size_t)kh * HD;

    for (int i = tid; i < 64 * 128; i += 256) {
        int r = i >> 7, c = i & 127;
        Qs[r * 129 + c] = Qb[(size_t)(q0 + r) * DMODEL + c] * scale;
    }
    if (tid < 64) { mrow[tid] = -INFINITY; lrow[tid] = 0.f; }

    float acc[32];
#pragma unroll
    for (int i = 0; i < 32; i++) acc[i] = 0.f;

    int orow = tid >> 2;
    int oc0  = (tid & 3) * 32;
    int str  = tid >> 4;
    int stc  = tid & 15;

    for (int kt = 0; kt <= qb; kt++) {
        int k0 = kt * 64;
        __syncthreads();
        for (int i = tid; i < 64 * 128; i += 256) {
            int r = i >> 7, c = i & 127;
            Ks[r * 129 + c] = Kb[(size_t)(k0 + r) * KVDIM + c];
            Vs[r * 128 + c] = Vb[(size_t)(k0 + r) * KVDIM + c];
        }
        __syncthreads();

        float s4[4][4];
#pragma unroll
        for (int i = 0; i < 4; i++)
#pragma unroll
            for (int j = 0; j < 4; j++) s4[i][j] = 0.f;

        const float* qp = &Qs[(str * 4) * 129];
        const float* kp = &Ks[(stc * 4) * 129];
#pragma unroll 4
        for (int kk = 0; kk < 128; kk++) {
            float ar[4], br[4];
#pragma unroll
            for (int i = 0; i < 4; i++) ar[i] = qp[i * 129 + kk];
#pragma unroll
            for (int j = 0; j < 4; j++) br[j] = kp[j * 129 + kk];
#pragma unroll
            for (int i = 0; i < 4; i++)
#pragma unroll
                for (int j = 0; j < 4; j++)
                    s4[i][j] = fmaf(ar[i], br[j], s4[i][j]);
        }

#pragma unroll
        for (int i = 0; i < 4; i++)
#pragma unroll
            for (int j = 0; j < 4; j++) {
                int qr = q0 + str * 4 + i;
                int kc = k0 + stc * 4 + j;
                Ss[(str * 4 + i) * 65 + stc * 4 + j] = (kc <= qr) ? s4[i][j] : -INFINITY;
            }
        __syncthreads();

        if (tid < 64) {
            int r = tid;
            float mold = mrow[r];
            float tmax = -INFINITY;
            for (int j = 0; j < 64; j++) tmax = fmaxf(tmax, Ss[r * 65 + j]);
            float nm  = fmaxf(mold, tmax);
            float al  = expf(mold - nm);
            float sum = 0.f;
            for (int j = 0; j < 64; j++) {
                float p = expf(Ss[r * 65 + j] - nm);
                Ss[r * 65 + j] = p;
                sum += p;
            }
            arow[r] = al;
            lrow[r] = lrow[r] * al + sum;
            mrow[r] = nm;
        }
        __syncthreads();

        float al = arow[orow];
#pragma unroll
        for (int i = 0; i < 32; i++) acc[i] *= al;

        const float* srow = &Ss[orow * 65];
#pragma unroll 4
        for (int j = 0; j < 64; j++) {
            float p = srow[j];
            const float4* vp = (const float4*)&Vs[j * 128 + oc0];
#pragma unroll
            for (int c4 = 0; c4 < 8; c4++) {
                float4 v = vp[c4];
                acc[c4 * 4 + 0] = fmaf(p, v.x, acc[c4 * 4 + 0]);
                acc[c4 * 4 + 1] = fmaf(p, v.y, acc[c4 * 4 + 1]);
                acc[c4 * 4 + 2] = fmaf(p, v.z, acc[c4 * 4 + 2]);
                acc[c4 * 4 + 3] = fmaf(p, v.w, acc[c4 * 4 + 3]);
            }
        }
    }

    float linv = 1.f / lrow[orow];
    float* Op = O + (size_t)(b * SEQ + q0 + orow) * DMODEL + h * HD + oc0;
#pragma unroll
    for (int c4 = 0; c4 < 8; c4++) {
        *(float4*)(Op + c4 * 4) = make_float4(acc[c4 * 4 + 0] * linv, acc[c4 * 4 + 1] * linv,
                                              acc[c4 * 4 + 2] * linv, acc[c4 * 4 + 3] * linv);
    }
}

// ---------------------------------------------------------------------------
extern "C" void kernel_launch(void* const* d_in, const int* in_sizes, int n_in,
                              void* d_out, int out_size)
{
    const float* x  = (const float*)d_in[0];
    const float* Wq = (const float*)d_in[2];
    const float* Wk = (const float*)d_in[3];
    const float* Wv = (const float*)d_in[4];
    const float* Wo = (const float*)d_in[5];
    float* out = (float*)d_out;

    float *gQ, *gK, *gV, *gA;
    __half *xh, *xl, *wq, *wk, *wv, *wo;
    cudaGetSymbolAddress((void**)&gQ, g_Q);
    cudaGetSymbolAddress((void**)&gK, g_K);
    cudaGetSymbolAddress((void**)&gV, g_V);
    cudaGetSymbolAddress((void**)&gA, g_A);
    cudaGetSymbolAddress((void**)&xh, g_Xhi);
    cudaGetSymbolAddress((void**)&xl, g_Xlo);
    cudaGetSymbolAddress((void**)&wq, g_Wq);
    cudaGetSymbolAddress((void**)&wk, g_Wk);
    cudaGetSymbolAddress((void**)&wv, g_Wv);
    cudaGetSymbolAddress((void**)&wo, g_Wo);

    cudaFuncSetAttribute(gemm_mma, cudaFuncAttributeMaxDynamicSharedMemorySize, GEMM_SMEM);

    // Conversions: x -> fp16 hi/lo, weights -> fp16 transposed
    int tot4 = ROWS * DMODEL / 4;
    conv_split_half<<<(tot4 + 255) / 256, 256>>>(x, xh, xl, tot4);
    conv_T_half<<<dim3(DMODEL / 32, DMODEL / 32), dim3(32, 8)>>>(Wq, wq, DMODEL, DMODEL);
    conv_T_half<<<dim3(KVDIM / 32, DMODEL / 32), dim3(32, 8)>>>(Wk, wk, DMODEL, KVDIM);
    conv_T_half<<<dim3(KVDIM / 32, DMODEL / 32), dim3(32, 8)>>>(Wv, wv, DMODEL, KVDIM);
    conv_T_half<<<dim3(DMODEL / 32, DMODEL / 32), dim3(32, 8)>>>(Wo, wo, DMODEL, DMODEL);

    // Projections on HMMA (fp16 2-product: (Ah+Al) @ Bh)
    gemm_mma<<<dim3(DMODEL / 128, ROWS / 128), 256, GEMM_SMEM>>>(xh, xl, wq, gQ, ROWS, DMODEL, DMODEL);
    gemm_mma<<<dim3(KVDIM / 128, ROWS / 128), 256, GEMM_SMEM>>>(xh, xl, wk, gK, ROWS, KVDIM, DMODEL);
    gemm_mma<<<dim3(KVDIM / 128, ROWS / 128), 256, GEMM_SMEM>>>(xh, xl, wv, gV, ROWS, KVDIM, DMODEL);

    // RoPE
    {
        int totQ = ROWS * NHEADS * 64;
        int totK = ROWS * NKV * 64;
        rope_kernel<<<(totQ + 255) / 256, 256>>>(gQ, NHEADS, totQ);
        rope_kernel<<<(totK + 255) / 256, 256>>>(gK, NKV, totK);
    }

    // Causal flash attention (fp32)
    size_t smem = (size_t)(64 * 129 * 2 + 64 * 128 + 64 * 65 + 3 * 64) * sizeof(float);
    cudaFuncSetAttribute(attn_kernel, cudaFuncAttributeMaxDynamicSharedMemorySize, (int)smem);
    attn_kernel<<<dim3(SEQ / 64, NHEADS, BATCH), 256, smem>>>(gQ, gK, gV, gA);

    // Output projection: split attn output, then HMMA GEMM
    conv_split_half<<<(tot4 + 255) / 256, 256>>>(gA, xh, xl, tot4);
    gemm_mma<<<dim3(DMODEL / 128, ROWS / 128), 256, GEMM_SMEM>>>(xh, xl, wo, out, ROWS, DMODEL, DMODEL);
}

// round 13
// speedup vs baseline: 6.8470x; 4.3095x over previous
#include <cuda_runtime.h>
#include <cuda_fp16.h>
#include <math.h>
#include <stdint.h>

#define BATCH   2
#define SEQ     2048
#define DMODEL  4096
#define NHEADS  32
#define NKV     8
#define HD      128
#define ROWS    (BATCH*SEQ)      // 4096
#define KVDIM   (NKV*HD)         // 1024

// ---------------- scratch (__device__ globals: allocation-free rule) -------
__device__ float g_Q[(size_t)ROWS * DMODEL];
__device__ float g_K[(size_t)ROWS * KVDIM];
__device__ float g_V[(size_t)ROWS * KVDIM];

__device__ __align__(16) __half g_Xhi[(size_t)ROWS * DMODEL];
__device__ __align__(16) __half g_Xlo[(size_t)ROWS * DMODEL];
__device__ __align__(16) __half g_Wq[(size_t)DMODEL * DMODEL];  // [N,K] fp16
__device__ __align__(16) __half g_Wk[(size_t)KVDIM * DMODEL];
__device__ __align__(16) __half g_Wv[(size_t)KVDIM * DMODEL];
__device__ __align__(16) __half g_Wo[(size_t)DMODEL * DMODEL];

__device__ __align__(16) __half g_Qh[(size_t)ROWS * DMODEL];
__device__ __align__(16) __half g_Ql[(size_t)ROWS * DMODEL];
__device__ __align__(16) __half g_Kh[(size_t)ROWS * KVDIM];
__device__ __align__(16) __half g_Kl[(size_t)ROWS * KVDIM];
__device__ __align__(16) __half g_Vh[(size_t)ROWS * KVDIM];
__device__ __align__(16) __half g_Vl[(size_t)ROWS * KVDIM];

// ---------------- PTX helpers (sm_80-era ISA: valid on compute_103) --------
__device__ __forceinline__ uint32_t smem_u32(const void* p) {
    uint32_t a;
    asm("{ .reg .u64 t; cvta.to.shared.u64 t, %1; cvt.u32.u64 %0, t; }" : "=r"(a) : "l"(p));
    return a;
}
__device__ __forceinline__ void cp16(uint32_t s, const void* g) {
    asm volatile("cp.async.cg.shared.global [%0], [%1], 16;" :: "r"(s), "l"(g));
}
#define CP_COMMIT() asm volatile("cp.async.commit_group;" ::: "memory")
#define CP_WAIT0()  asm volatile("cp.async.wait_group 0;" ::: "memory")
#define CP_WAIT1()  asm volatile("cp.async.wait_group 1;" ::: "memory")

__device__ __forceinline__ void ldm_x4(uint32_t* r, uint32_t a) {
    asm volatile("ldmatrix.sync.aligned.m8n8.x4.shared.b16 {%0,%1,%2,%3}, [%4];"
                 : "=r"(r[0]), "=r"(r[1]), "=r"(r[2]), "=r"(r[3]) : "r"(a));
}
__device__ __forceinline__ void ldm_x2(uint32_t* r, uint32_t a) {
    asm volatile("ldmatrix.sync.aligned.m8n8.x2.shared.b16 {%0,%1}, [%2];"
                 : "=r"(r[0]), "=r"(r[1]) : "r"(a));
}
__device__ __forceinline__ void ldm_x4t(uint32_t* r, uint32_t a) {
    asm volatile("ldmatrix.sync.aligned.m8n8.x4.trans.shared.b16 {%0,%1,%2,%3}, [%4];"
                 : "=r"(r[0]), "=r"(r[1]), "=r"(r[2]), "=r"(r[3]) : "r"(a));
}
__device__ __forceinline__ void mma16816(float* d, const uint32_t* a, const uint32_t* b) {
    asm volatile(
        "mma.sync.aligned.m16n8k16.row.col.f32.f16.f16.f32 "
        "{%0,%1,%2,%3}, {%4,%5,%6,%7}, {%8,%9}, {%0,%1,%2,%3};"
        : "+f"(d[0]), "+f"(d[1]), "+f"(d[2]), "+f"(d[3])
        : "r"(a[0]), "r"(a[1]), "r"(a[2]), "r"(a[3]), "r"(b[0]), "r"(b[1]));
}
__device__ __forceinline__ uint32_t packh(__half a, __half b) {
    __half2 t = __halves2half2(a, b);
    return *(uint32_t*)&t;
}

// ---------------- conversion kernels ---------------------------------------
__global__ void conv_split_half(const float* __restrict__ X, __half* __restrict__ hi,
                                __half* __restrict__ lo, int total4)
{
    int i = blockIdx.x * blockDim.x + threadIdx.x;
    if (i >= total4) return;
    float4 v = ((const float4*)X)[i];
    float f[4] = {v.x, v.y, v.z, v.w};
    __half h[4], l[4];
#pragma unroll
    for (int j = 0; j < 4; j++) {
        h[j] = __float2half_rn(f[j]);
        l[j] = __float2half_rn(f[j] - __half2float(h[j]));
    }
    ((uint2*)hi)[i] = *(uint2*)h;
    ((uint2*)lo)[i] = *(uint2*)l;
}

__global__ void conv_T_half(const float* __restrict__ W, __half* __restrict__ hi,
                            int K, int N)
{
    __shared__ float t[32][33];
    int n0 = blockIdx.x * 32, k0 = blockIdx.y * 32;
    int tx = threadIdx.x, ty = threadIdx.y;
#pragma unroll
    for (int i = 0; i < 32; i += 8)
        t[ty + i][tx] = W[(size_t)(k0 + ty + i) * N + n0 + tx];
    __syncthreads();
#pragma unroll
    for (int i = 0; i < 32; i += 8)
        hi[(size_t)(n0 + ty + i) * K + k0 + tx] = __float2half_rn(t[tx][ty + i]);
}

// RoPE + split: X fp32 [ROWS, nh*128] -> (hi,lo) fp16, scale folded in.
__global__ void rope_split(const float* __restrict__ X, __half* __restrict__ xh,
                           __half* __restrict__ xl, int nh, float scale, int total)
{
    int idx = blockIdx.x * blockDim.x + threadIdx.x;
    if (idx >= total) return;
    int d   = idx & 63;
    int h   = (idx >> 6) % nh;
    int row = idx / (64 * nh);
    int s   = row & (SEQ - 1);
    float inv = expf(-(float)d * (9.210340371976184f / 64.f));
    float sn, cs;
    sincosf((float)s * inv, &sn, &cs);
    size_t base = (size_t)row * (nh * HD) + h * HD + d;
    float x0 = X[base], x1 = X[base + 64];
    float r0 = (x0 * cs - x1 * sn) * scale;
    float r1 = (x1 * cs + x0 * sn) * scale;
    __half h0 = __float2half_rn(r0);
    __half h1 = __float2half_rn(r1);
    xh[base]      = h0;
    xl[base]      = __float2half_rn(r0 - __half2float(h0));
    xh[base + 64] = h1;
    xl[base + 64] = __float2half_rn(r1 - __half2float(h1));
}

// ---------------- mma.sync fp16 2-product GEMM (unchanged, passing) --------
#define TSTRIDE 80
#define TILE_B  (128 * TSTRIDE)
#define STAGE_B (3 * TILE_B)
#define GEMM_SMEM (3 * STAGE_B)

__device__ __forceinline__ void ld_stage(uint32_t sst,
    const __half* __restrict__ Ah, const __half* __restrict__ Al,
    const __half* __restrict__ Bh, int m0, int n0, int K, int k0, int tid)
{
#pragma unroll
    for (int it = 0; it < 6; it++) {
        int idx  = tid + it * 256;
        int tile = idx >> 9;
        int r    = (idx >> 2) & 127;
        int j    = idx & 3;
        const __half* g = (tile == 0) ? Ah : ((tile == 1) ? Al : Bh);
        int row0 = (tile == 2) ? n0 : m0;
        cp16(sst + (uint32_t)(tile * TILE_B + r * TSTRIDE + j * 16),
             g + (size_t)(row0 + r) * K + k0 + j * 8);
    }
}

__global__ __launch_bounds__(256, 2) void gemm_mma(
    const __half* __restrict__ Ahi, const __half* __restrict__ Alo,
    const __half* __restrict__ Bhi,
    float* __restrict__ C, int M, int N, int K)
{
    extern __shared__ char smc[];
    uint32_t smb = smem_u32(smc);
    int tid  = threadIdx.x;
    int lane = tid & 31, wid = tid >> 5;
    int m0 = blockIdx.y * 128, n0 = blockIdx.x * 128;
    int wm = (wid & 1) * 64;
    int wn = (wid >> 1) * 32;

    int aR = wm + (lane & 15);
    int aC = (lane >> 4);
    int bR = wn + (lane & 7);
    int bC = (lane >> 3) & 1;

    float acc[4][4][4];
#pragma unroll
    for (int mt = 0; mt < 4; mt++)
#pragma unroll
        for (int nt = 0; nt < 4; nt++)
#pragma unroll
            for (int q = 0; q < 4; q++) acc[mt][nt][q] = 0.f;

    int NC = K >> 5;
    ld_stage(smb,           Ahi, Alo, Bhi, m0, n0, K, 0,  tid); CP_COMMIT();
    ld_stage(smb + STAGE_B, Ahi, Alo, Bhi, m0, n0, K, 32, tid); CP_COMMIT();

    for (int c = 0; c < NC; c++) {
        if (c + 1 < NC) CP_WAIT1(); else CP_WAIT0();
        __syncthreads();
        if (c + 2 < NC) {
            ld_stage(smb + (uint32_t)(((c + 2) % 3) * STAGE_B),
                     Ahi, Alo, Bhi, m0, n0, K, (c + 2) << 5, tid);
            CP_COMMIT();
        }
        uint32_t sst = smb + (uint32_t)((c % 3) * STAGE_B);
#pragma unroll
        for (int ks = 0; ks < 2; ks++) {
            int jb = ks * 2;
            uint32_t ah[4][4], al[4][4], bh[4][2];
#pragma unroll
            for (int mt = 0; mt < 4; mt++)
                ldm_x4(ah[mt], sst + (uint32_t)((aR + mt * 16) * TSTRIDE + (jb + aC) * 16));
#pragma unroll
            for (int nt = 0; nt < 4; nt++)
                ldm_x2(bh[nt], sst + 2 * TILE_B + (uint32_t)((bR + nt * 8) * TSTRIDE + (jb + bC) * 16));
#pragma unroll
            for (int mt = 0; mt < 4; mt++)
                ldm_x4(al[mt], sst + TILE_B + (uint32_t)((aR + mt * 16) * TSTRIDE + (jb + aC) * 16));
#pragma unroll
            for (int mt = 0; mt < 4; mt++)
#pragma unroll
                for (int nt = 0; nt < 4; nt++)
                    mma16816(acc[mt][nt], ah[mt], bh[nt]);
#pragma unroll
            for (int mt = 0; mt < 4; mt++)
#pragma unroll
                for (int nt = 0; nt < 4; nt++)
                    mma16816(acc[mt][nt], al[mt], bh[nt]);
        }
    }

    int gr = lane >> 2, gc = (lane & 3) * 2;
#pragma unroll
    for (int mt = 0; mt < 4; mt++) {
#pragma unroll
        for (int nt = 0; nt < 4; nt++) {
            size_t r0 = (size_t)(m0 + wm + mt * 16 + gr) * N + n0 + wn + nt * 8 + gc;
            size_t r1 = r0 + (size_t)8 * N;
            *(float2*)(C + r0) = make_float2(acc[mt][nt][0], acc[mt][nt][1]);
            *(float2*)(C + r1) = make_float2(acc[mt][nt][2], acc[mt][nt][3]);
        }
    }
}

// ---------------- HMMA flash attention -------------------------------------
// Q tile 128, K tile 64. 8 warps, warp w owns q rows [w*16, w*16+16).
// QK: 3-product fp16; PV: 3-product (Ph,Pl x Vh + Ph x Vl). fp32 softmax.
#define QT 128
#define KT 64
#define ASTR 272                          // bytes per smem row (128 fp16 + pad)
#define AQ_TILE  (128 * ASTR)             // 34816
#define AKV_TILE (64 * ASTR)              // 17408
#define AKV_STG  (4 * AKV_TILE)           // Kh,Kl,Vh,Vl = 69632
#define ATTN_SMEM (2 * AQ_TILE + 2 * AKV_STG)   // 208896

__device__ __forceinline__ void ld_kv(uint32_t st,
    const __half* __restrict__ Kh, const __half* __restrict__ Kl,
    const __half* __restrict__ Vh, const __half* __restrict__ Vl,
    int k0, int tid)
{
#pragma unroll
    for (int it = 0; it < 16; it++) {
        int idx = tid + it * 256;
        int t = idx >> 10;                // 0..3
        int r = (idx >> 4) & 63;
        int j = idx & 15;
        const __half* g = (t == 0) ? Kh : ((t == 1) ? Kl : ((t == 2) ? Vh : Vl));
        cp16(st + (uint32_t)(t * AKV_TILE + r * ASTR + j * 16),
             g + (size_t)(k0 + r) * KVDIM + j * 8);
    }
}

__global__ __launch_bounds__(256) void attn_mma(
    const __half* __restrict__ Qh_, const __half* __restrict__ Ql_,
    const __half* __restrict__ Kh_, const __half* __restrict__ Kl_,
    const __half* __restrict__ Vh_, const __half* __restrict__ Vl_,
    __half* __restrict__ Oh_, __half* __restrict__ Ol_)
{
    extern __shared__ char smc[];
    uint32_t smb = smem_u32(smc);
    int tid = threadIdx.x, lane = tid & 31, w = tid >> 5;
    int qb = blockIdx.x, h = blockIdx.y, b = blockIdx.z;
    int kh = h >> 2;
    int q0 = qb * QT;

    const __half* Qhg = Qh_ + (size_t)b * SEQ * DMODEL + (size_t)h * HD;
    const __half* Qlg = Ql_ + (size_t)b * SEQ * DMODEL + (size_t)h * HD;
    const __half* Khg = Kh_ + (size_t)b * SEQ * KVDIM + (size_t)kh * HD;
    const __half* Klg = Kl_ + (size_t)b * SEQ * KVDIM + (size_t)kh * HD;
    const __half* Vhg = Vh_ + (size_t)b * SEQ * KVDIM + (size_t)kh * HD;
    const __half* Vlg = Vl_ + (size_t)b * SEQ * KVDIM + (size_t)kh * HD;

    uint32_t sQh = smb, sQl = smb + AQ_TILE;
    uint32_t sS0 = smb + 2 * AQ_TILE;
    uint32_t sS1 = sS0 + AKV_STG;

    // Q tile (hi+lo) via cp.async
#pragma unroll
    for (int it = 0; it < 16; it++) {
        int idx = tid + it * 256;
        int t = idx >> 11;
        int r = (idx >> 4) & 127;
        int j = idx & 15;
        cp16((t ? sQl : sQh) + (uint32_t)(r * ASTR + j * 16),
             (t ? Qlg : Qhg) + (size_t)(q0 + r) * DMODEL + j * 8);
    }
    ld_kv(sS0, Khg, Klg, Vhg, Vlg, 0, tid);
    CP_COMMIT();                          // c0 = Q + KV0
    ld_kv(sS1, Khg, Klg, Vhg, Vlg, KT, tid);
    CP_COMMIT();                          // c1 = KV1

    int NT = 2 * (qb + 1);

    float oacc[16][4];
#pragma unroll
    for (int i = 0; i < 16; i++)
#pragma unroll
        for (int q = 0; q < 4; q++) oacc[i][q] = 0.f;
    float m0 = -INFINITY, m1 = -INFINITY, l0 = 0.f, l1 = 0.f;
    int gr = lane >> 2, gc = (lane & 3) * 2;
    int row0 = q0 + w * 16 + gr, row1 = row0 + 8;

    uint32_t aoff = (uint32_t)((w * 16 + (lane & 15)) * ASTR + (lane >> 4) * 16);
    uint32_t boff = (uint32_t)((lane & 7) * ASTR + ((lane >> 3) & 1) * 16);
    uint32_t voffb = (uint32_t)((((lane >> 3) & 1) * 8 + (lane & 7)) * ASTR + (lane >> 4) * 16);

    for (int kt = 0; kt < NT; kt++) {
        if (kt + 1 < NT) CP_WAIT1(); else CP_WAIT0();
        __syncthreads();
        uint32_t st = (kt & 1) ? sS1 : sS0;
        uint32_t sKh = st, sKl = st + AKV_TILE, sVh = st + 2 * AKV_TILE, sVl = st + 3 * AKV_TILE;
        int k0 = kt * KT;

        // ---- scores S = Q K^T (3-product fp16) ----
        float sacc[8][4];
#pragma unroll
        for (int nt = 0; nt < 8; nt++)
#pragma unroll
            for (int q = 0; q < 4; q++) sacc[nt][q] = 0.f;

#pragma unroll
        for (int ks = 0; ks < 8; ks++) {
            uint32_t qa = aoff + ks * 32;
            uint32_t qh4[4], ql4[4];
            ldm_x4(qh4, sQh + qa);
            ldm_x4(ql4, sQl + qa);
#pragma unroll
            for (int nt = 0; nt < 8; nt++) {
                uint32_t ka = boff + (uint32_t)(nt * 8 * ASTR) + ks * 32;
                uint32_t kh2[2], kl2[2];
                ldm_x2(kh2, sKh + ka);
                ldm_x2(kl2, sKl + ka);
                mma16816(sacc[nt], qh4, kh2);
                mma16816(sacc[nt], qh4, kl2);
                mma16816(sacc[nt], ql4, kh2);
            }
        }

        // ---- causal mask ----
#pragma unroll
        for (int nt = 0; nt < 8; nt++) {
            int col = k0 + nt * 8 + gc;
            if (col > row0)     sacc[nt][0] = -INFINITY;
            if (col + 1 > row0) sacc[nt][1] = -INFINITY;
            if (col > row1)     sacc[nt][2] = -INFINITY;
            if (col + 1 > row1) sacc[nt][3] = -INFINITY;
        }

        // ---- online softmax (register, per 2 rows) ----
        float t0 = -INFINITY, t1 = -INFINITY;
#pragma unroll
        for (int nt = 0; nt < 8; nt++) {
            t0 = fmaxf(t0, fmaxf(sacc[nt][0], sacc[nt][1]));
            t1 = fmaxf(t1, fmaxf(sacc[nt][2], sacc[nt][3]));
        }
        t0 = fmaxf(t0, __shfl_xor_sync(0xFFFFFFFF, t0, 1));
        t0 = fmaxf(t0, __shfl_xor_sync(0xFFFFFFFF, t0, 2));
        t1 = fmaxf(t1, __shfl_xor_sync(0xFFFFFFFF, t1, 1));
        t1 = fmaxf(t1, __shfl_xor_sync(0xFFFFFFFF, t1, 2));
        float nm0 = fmaxf(m0, t0), nm1 = fmaxf(m1, t1);
        float a0 = __expf(m0 - nm0), a1 = __expf(m1 - nm1);
        float s0 = 0.f, s1 = 0.f;
#pragma unroll
        for (int nt = 0; nt < 8; nt++) {
            sacc[nt][0] = __expf(sacc[nt][0] - nm0);
            sacc[nt][1] = __expf(sacc[nt][1] - nm0);
            sacc[nt][2] = __expf(sacc[nt][2] - nm1);
            sacc[nt][3] = __expf(sacc[nt][3] - nm1);
            s0 += sacc[nt][0] + sacc[nt][1];
            s1 += sacc[nt][2] + sacc[nt][3];
        }
        s0 += __shfl_xor_sync(0xFFFFFFFF, s0, 1);
        s0 += __shfl_xor_sync(0xFFFFFFFF, s0, 2);
        s1 += __shfl_xor_sync(0xFFFFFFFF, s1, 1);
        s1 += __shfl_xor_sync(0xFFFFFFFF, s1, 2);
        l0 = l0 * a0 + s0; l1 = l1 * a1 + s1;
        m0 = nm0; m1 = nm1;
#pragma unroll
        for (int nt = 0; nt < 16; nt++) {
            oacc[nt][0] *= a0; oacc[nt][1] *= a0;
            oacc[nt][2] *= a1; oacc[nt][3] *= a1;
        }

        // ---- P fragments (hi + lo) ----
        uint32_t ph[4][4], pl[4][4];
#pragma unroll
        for (int kk = 0; kk < 4; kk++) {
#pragma unroll
            for (int hl = 0; hl < 2; hl++) {
                int nt = kk * 2 + hl;
                __half h0 = __float2half_rn(sacc[nt][0]);
                __half h1v = __float2half_rn(sacc[nt][1]);
                __half h2v = __float2half_rn(sacc[nt][2]);
                __half h3v = __float2half_rn(sacc[nt][3]);
                ph[kk][hl * 2 + 0] = packh(h0, h1v);       // row gr
                ph[kk][hl * 2 + 1] = packh(h2v, h3v);      // row gr+8
                pl[kk][hl * 2 + 0] = packh(__float2half_rn(sacc[nt][0] - __half2float(h0)),
                                           __float2half_rn(sacc[nt][1] - __half2float(h1v)));
                pl[kk][hl * 2 + 1] = packh(__float2half_rn(sacc[nt][2] - __half2float(h2v)),
                                           __float2half_rn(sacc[nt][3] - __half2float(h3v)));
            }
        }

        // ---- O += P V (3-product) ----
#pragma unroll
        for (int kk = 0; kk < 4; kk++) {
            uint32_t voff = voffb + (uint32_t)(kk * 16 * ASTR);
#pragma unroll
            for (int nt2 = 0; nt2 < 8; nt2++) {
                uint32_t va = voff + nt2 * 32;
                uint32_t vh4[4], vl4[4];
                ldm_x4t(vh4, sVh + va);
                ldm_x4t(vl4, sVl + va);
                mma16816(oacc[nt2 * 2],     ph[kk], vh4);
                mma16816(oacc[nt2 * 2],     pl[kk], vh4);
                mma16816(oacc[nt2 * 2],     ph[kk], vl4);
                mma16816(oacc[nt2 * 2 + 1], ph[kk], vh4 + 2);
                mma16816(oacc[nt2 * 2 + 1], pl[kk], vh4 + 2);
                mma16816(oacc[nt2 * 2 + 1], ph[kk], vl4 + 2);
            }
        }

        __syncthreads();
        if (kt + 2 < NT) {
            ld_kv((kt & 1) ? sS1 : sS0, Khg, Klg, Vhg, Vlg, (kt + 2) * KT, tid);
            CP_COMMIT();
        }
    }

    // ---- epilogue: O/l -> (hi,lo) fp16 ----
    float inv0 = 1.f / l0, inv1 = 1.f / l1;
    size_t ob = (size_t)(b * SEQ + q0 + w * 16) * DMODEL + h * HD;
#pragma unroll
    for (int nt = 0; nt < 16; nt++) {
        int c = nt * 8 + gc;
        size_t i0 = ob + (size_t)gr * DMODEL + c;
        size_t i1 = ob + (size_t)(gr + 8) * DMODEL + c;
        float v0 = oacc[nt][0] * inv0, v1 = oacc[nt][1] * inv0;
        float v2 = oacc[nt][2] * inv1, v3 = oacc[nt][3] * inv1;
        __half h0 = __float2half_rn(v0), h1v = __float2half_rn(v1);
        __half h2v = __float2half_rn(v2), h3v = __float2half_rn(v3);
        *(__half2*)(Oh_ + i0) = __halves2half2(h0, h1v);
        *(__half2*)(Ol_ + i0) = __halves2half2(__float2half_rn(v0 - __half2float(h0)),
                                               __float2half_rn(v1 - __half2float(h1v)));
        *(__half2*)(Oh_ + i1) = __halves2half2(h2v, h3v);
        *(__half2*)(Ol_ + i1) = __halves2half2(__float2half_rn(v2 - __half2float(h2v)),
                                               __float2half_rn(v3 - __half2float(h3v)));
    }
}

// ---------------------------------------------------------------------------
extern "C" void kernel_launch(void* const* d_in, const int* in_sizes, int n_in,
                              void* d_out, int out_size)
{
    const float* x  = (const float*)d_in[0];
    const float* Wq = (const float*)d_in[2];
    const float* Wk = (const float*)d_in[3];
    const float* Wv = (const float*)d_in[4];
    const float* Wo = (const float*)d_in[5];
    float* out = (float*)d_out;

    float *gQ, *gK, *gV;
    __half *xh, *xl, *wq, *wk, *wv, *wo, *qh, *ql, *kx, *kl, *vh, *vl;
    cudaGetSymbolAddress((void**)&gQ, g_Q);
    cudaGetSymbolAddress((void**)&gK, g_K);
    cudaGetSymbolAddress((void**)&gV, g_V);
    cudaGetSymbolAddress((void**)&xh, g_Xhi);
    cudaGetSymbolAddress((void**)&xl, g_Xlo);
    cudaGetSymbolAddress((void**)&wq, g_Wq);
    cudaGetSymbolAddress((void**)&wk, g_Wk);
    cudaGetSymbolAddress((void**)&wv, g_Wv);
    cudaGetSymbolAddress((void**)&wo, g_Wo);
    cudaGetSymbolAddress((void**)&qh, g_Qh);
    cudaGetSymbolAddress((void**)&ql, g_Ql);
    cudaGetSymbolAddress((void**)&kx, g_Kh);
    cudaGetSymbolAddress((void**)&kl, g_Kl);
    cudaGetSymbolAddress((void**)&vh, g_Vh);
    cudaGetSymbolAddress((void**)&vl, g_Vl);

    cudaFuncSetAttribute(gemm_mma, cudaFuncAttributeMaxDynamicSharedMemorySize, GEMM_SMEM);
    cudaFuncSetAttribute(attn_mma, cudaFuncAttributeMaxDynamicSharedMemorySize, ATTN_SMEM);

    // Conversions
    int tot4 = ROWS * DMODEL / 4;
    conv_split_half<<<(tot4 + 255) / 256, 256>>>(x, xh, xl, tot4);
    conv_T_half<<<dim3(DMODEL / 32, DMODEL / 32), dim3(32, 8)>>>(Wq, wq, DMODEL, DMODEL);
    conv_T_half<<<dim3(KVDIM / 32, DMODEL / 32), dim3(32, 8)>>>(Wk, wk, DMODEL, KVDIM);
    conv_T_half<<<dim3(KVDIM / 32, DMODEL / 32), dim3(32, 8)>>>(Wv, wv, DMODEL, KVDIM);
    conv_T_half<<<dim3(DMODEL / 32, DMODEL / 32), dim3(32, 8)>>>(Wo, wo, DMODEL, DMODEL);

    // Projections (HMMA, fp16 2-product)
    gemm_mma<<<dim3(DMODEL / 128, ROWS / 128), 256, GEMM_SMEM>>>(xh, xl, wq, gQ, ROWS, DMODEL, DMODEL);
    gemm_mma<<<dim3(KVDIM / 128, ROWS / 128), 256, GEMM_SMEM>>>(xh, xl, wk, gK, ROWS, KVDIM, DMODEL);
    gemm_mma<<<dim3(KVDIM / 128, ROWS / 128), 256, GEMM_SMEM>>>(xh, xl, wv, gV, ROWS, KVDIM, DMODEL);

    // RoPE + hi/lo split (softmax scale folded into Q)
    {
        int totQ = ROWS * NHEADS * 64;
        int totK = ROWS * NKV * 64;
        const float scale = 0.08838834764831845f;
        rope_split<<<(totQ + 255) / 256, 256>>>(gQ, qh, ql, NHEADS, scale, totQ);
        rope_split<<<(totK + 255) / 256, 256>>>(gK, kx, kl, NKV, 1.0f, totK);
        int totV4 = ROWS * KVDIM / 4;
        conv_split_half<<<(totV4 + 255) / 256, 256>>>(gV, vh, vl, totV4);
    }

    // HMMA flash attention -> (hi,lo) fp16 output (reuses x buffers)
    attn_mma<<<dim3(SEQ / QT, NHEADS, BATCH), 256, ATTN_SMEM>>>(qh, ql, kx, kl, vh, vl, xh, xl);

    // Output projection
    gemm_mma<<<dim3(DMODEL / 128, ROWS / 128), 256, GEMM_SMEM>>>(xh, xl, wo, out, ROWS, DMODEL, DMODEL);
}